// round 3
// baseline (speedup 1.0000x reference)
#include <cuda_runtime.h>
#include <cstdint>

// ---------------------------------------------------------------------------
// NodePredictor: y[b,n,:] = x[b,n,:] @ W[n] + b[n], out = y reshaped [B, N*DOUT]
// B=2048, N=64, DIN=DOUT=512, fp32.
//
// sm_100 (no 'a') target: legacy path cp.async + ldmatrix + mma.m16n8k8 tf32.
// R3: register double-buffering of A/B fragments (CUTLASS sm80 mainloop) to
// hide ldsm(29cyc)+cvt(4cyc) latency under the 16 MMAs of the previous ks.
// ---------------------------------------------------------------------------

static constexpr int B_DIM   = 2048;
static constexpr int N_NODES = 64;
static constexpr int DIN     = 512;
static constexpr int DOUT    = 512;
static constexpr int OUT_W   = N_NODES * DOUT;   // 32768

static constexpr int TILE_M  = 128;
static constexpr int TILE_N  = 128;
static constexpr int TILE_K  = 32;               // 32 tf32 = 128 B row
static constexpr int K_ITERS = DIN / TILE_K;     // 16
static constexpr int THREADS = 256;
static constexpr int STAGES  = 3;

static constexpr int STAGE_BYTES = 32768;        // A 16KB + B 16KB
static constexpr int SMEM_BIAS   = STAGES * STAGE_BYTES;          // 98304
static constexpr int SMEM_TOTAL  = SMEM_BIAS + TILE_N * 4;        // +512

// 64 MB scratch: Wt[n][dout][din], tf32(RNA)-rounded fp32 bits
__device__ float g_Wt[(size_t)N_NODES * DOUT * DIN];

// ---------------------------------------------------------------------------
__device__ __forceinline__ uint32_t smem_u32(const void* p) {
    uint32_t a;
    asm("{ .reg .u64 t; cvta.to.shared.u64 t, %1; cvt.u32.u64 %0, t; }" : "=r"(a) : "l"(p));
    return a;
}
__device__ __forceinline__ uint32_t rna_tf32(float x) {
    uint32_t r;
    asm("cvt.rna.tf32.f32 %0, %1;" : "=r"(r) : "f"(x));
    return r;
}
__device__ __forceinline__ uint32_t sw128(uint32_t off) {
    return off ^ ((off >> 3) & 0x70u);
}
__device__ __forceinline__ void cp_async16(uint32_t smem_dst, const void* gmem_src) {
    asm volatile("cp.async.cg.shared.global [%0], [%1], 16;"
                 :: "r"(smem_dst), "l"(gmem_src) : "memory");
}
__device__ __forceinline__ void cp_commit() {
    asm volatile("cp.async.commit_group;" ::: "memory");
}
template <int N>
__device__ __forceinline__ void cp_wait() {
    asm volatile("cp.async.wait_group %0;" :: "n"(N) : "memory");
}
__device__ __forceinline__ void ldsm_x4(uint32_t* r, uint32_t addr) {
    asm volatile("ldmatrix.sync.aligned.m8n8.x4.shared.b16 {%0,%1,%2,%3}, [%4];"
                 : "=r"(r[0]), "=r"(r[1]), "=r"(r[2]), "=r"(r[3]) : "r"(addr));
}
__device__ __forceinline__ void mma_tf32(float* c, const uint32_t* a, uint32_t b0, uint32_t b1) {
    asm volatile(
        "mma.sync.aligned.m16n8k8.row.col.f32.tf32.tf32.f32 "
        "{%0,%1,%2,%3}, {%4,%5,%6,%7}, {%8,%9}, {%0,%1,%2,%3};"
        : "+f"(c[0]), "+f"(c[1]), "+f"(c[2]), "+f"(c[3])
        : "r"(a[0]), "r"(a[1]), "r"(a[2]), "r"(a[3]), "r"(b0), "r"(b1));
}

// ---------------------------------------------------------------------------
// Pre-pass: Wt[n][o][i] = rna_tf32(W[n][i][o])
// ---------------------------------------------------------------------------
__global__ void wt_transpose_kernel(const float* __restrict__ W) {
    __shared__ float tile[32][33];
    const int n  = blockIdx.z;
    const int i0 = blockIdx.x * 32;
    const int o0 = blockIdx.y * 32;
    const int tx = threadIdx.x, ty = threadIdx.y;   // 32 x 8

    const float* src = W + ((size_t)n * DIN + i0) * DOUT + o0;
#pragma unroll
    for (int r = 0; r < 32; r += 8)
        tile[ty + r][tx] = src[(size_t)(ty + r) * DOUT + tx];
    __syncthreads();

    float* dst = g_Wt + ((size_t)n * DOUT + o0) * DIN + i0;
#pragma unroll
    for (int r = 0; r < 32; r += 8)
        dst[(size_t)(ty + r) * DIN + tx] = __uint_as_float(rna_tf32(tile[tx][ty + r]));
}

// ---------------------------------------------------------------------------
// Main GEMM: CTA = [128M x 128N] tile of one node. 8 warps, warptile 64x32.
// ---------------------------------------------------------------------------
__global__ __launch_bounds__(THREADS, 2)
void node_gemm_kernel(const float* __restrict__ x, const float* __restrict__ bias,
                      float* __restrict__ out) {
    extern __shared__ char smem[];
    const uint32_t sbase = smem_u32(smem);
    const int tid  = threadIdx.x;
    const int wid  = tid >> 5;
    const int lane = tid & 31;

    // block decode: nt fastest (L2 reuse of A slab), then mt, then node
    const int bx = blockIdx.x;
    const int n  = bx >> 6;
    const int mt = (bx >> 2) & 15;
    const int nt = bx & 3;
    const int m_base = mt * TILE_M;
    const int o_base = nt * TILE_N;

    if (tid < TILE_N)
        reinterpret_cast<float*>(smem + SMEM_BIAS)[tid] = bias[n * DOUT + o_base + tid];

    // ---- cp.async staging: thread t stages row t/2, chunks (t&1)*4..+3
    const int st_row = tid >> 1;
    const int st_cb  = (tid & 1) * 4;
    const float* a_src = x + ((size_t)(m_base + st_row) * N_NODES + n) * DIN + st_cb * 4;
    const float* b_src = g_Wt + ((size_t)(n * DOUT + o_base + st_row)) * DIN + st_cb * 4;
    uint32_t st_dst[4];
#pragma unroll
    for (int j = 0; j < 4; ++j)
        st_dst[j] = sw128((uint32_t)st_row * 128u + (uint32_t)(st_cb + j) * 16u);

    auto issue = [&](int stage, int kc) {
        const uint32_t as = sbase + stage * STAGE_BYTES;
        const uint32_t bs = as + 16384;
        const float* ap = a_src + kc * TILE_K;
        const float* bp = b_src + kc * TILE_K;
#pragma unroll
        for (int j = 0; j < 4; ++j) cp_async16(as + st_dst[j], ap + j * 4);
#pragma unroll
        for (int j = 0; j < 4; ++j) cp_async16(bs + st_dst[j], bp + j * 4);
        cp_commit();
    };

    // ---- ldmatrix lane address components (same mapping as R2, verified)
    const int wm = wid >> 2;       // 0..1  (M)
    const int wn = wid & 3;        // 0..3  (N)
    const uint32_t a_row  = (uint32_t)(wm * 64 + (lane & 15));
    const uint32_t a_cadd = (uint32_t)(lane >> 4);
    const uint32_t b_row  = (uint32_t)(wn * 32 + ((lane >> 4) << 3) + (lane & 7));
    const uint32_t b_cadd = (uint32_t)((lane >> 3) & 1);

    // double-buffered fragments + accumulators
    uint32_t afr[2][4][4];
    uint32_t bfr[2][8];
    float c[4][4][4];
#pragma unroll
    for (int i = 0; i < 4; ++i)
#pragma unroll
        for (int j = 0; j < 4; ++j)
#pragma unroll
            for (int k = 0; k < 4; ++k) c[i][j][k] = 0.0f;

    // ldsm-only fragment load (no cvt) — buf index must be compile-time
    auto ldsm_frags = [&](int nb, uint32_t as, uint32_t bs, int ks) {
        const uint32_t ac = 2 * (uint32_t)ks + a_cadd;
        const uint32_t bc = 2 * (uint32_t)ks + b_cadd;
#pragma unroll
        for (int m = 0; m < 4; ++m)
            ldsm_x4(afr[nb][m], as + sw128((a_row + m * 16) * 128u + ac * 16u));
        ldsm_x4(bfr[nb] + 0, bs + sw128((b_row +  0) * 128u + bc * 16u));
        ldsm_x4(bfr[nb] + 4, bs + sw128((b_row + 16) * 128u + bc * 16u));
    };
    auto cvt_a = [&](int nb) {
#pragma unroll
        for (int m = 0; m < 4; ++m)
#pragma unroll
            for (int r = 0; r < 4; ++r)
                afr[nb][m][r] = rna_tf32(__uint_as_float(afr[nb][m][r]));
    };
    auto mma16 = [&](int cb) {
#pragma unroll
        for (int m = 0; m < 4; ++m)
#pragma unroll
            for (int q = 0; q < 4; ++q)
                mma_tf32(c[m][q], afr[cb][m], bfr[cb][2 * q], bfr[cb][2 * q + 1]);
    };

    // ---- prologue: fill 2 stages, load frags for (kc=0, ks=0) into buf 0
    issue(0, 0);
    issue(1, 1);
    cp_wait<1>();
    __syncthreads();
    {
        const uint32_t as = sbase, bs = sbase + 16384;
        ldsm_frags(0, as, bs, 0);
        cvt_a(0);
    }

    int s = 0;
    for (int kc = 0; kc < K_ITERS; ++kc) {
        const int s_next  = (s + 1 == STAGES) ? 0 : s + 1;
        const int s_issue = (s + 2 >= STAGES) ? s + 2 - STAGES : s + 2;
        const uint32_t as  = sbase + s * STAGE_BYTES,       bs  = as + 16384;
        const uint32_t asn = sbase + s_next * STAGE_BYTES,  bsn = asn + 16384;

        if (kc + 2 < K_ITERS) issue(s_issue, kc + 2);

#pragma unroll
        for (int ks = 0; ks < 4; ++ks) {
            const int cb = ks & 1;
            const int nb = cb ^ 1;
            if (ks < 3) {
                ldsm_frags(nb, as, bs, ks + 1);   // prefetch next ks
                mma16(cb);                        // hide ldsm latency
                cvt_a(nb);                        // off the mma critical path
            } else if (kc + 1 < K_ITERS) {
                if (kc + 1 == K_ITERS - 1) cp_wait<0>(); else cp_wait<1>();
                __syncthreads();
                ldsm_frags(nb, asn, bsn, 0);      // first frags of next stage
                mma16(cb);
                cvt_a(nb);
            } else {
                mma16(cb);                        // final ks, nothing to prefetch
            }
        }
        s = s_next;
    }

    // ---- epilogue: add bias, store (c0,c1)/(c2,c3) as float2
    const float* bsm = reinterpret_cast<const float*>(smem + SMEM_BIAS);
    const int r_top = m_base + wm * 64 + (lane >> 2);
    const int lc0   = wn * 32 + (lane & 3) * 2;
#pragma unroll
    for (int m = 0; m < 4; ++m) {
#pragma unroll
        for (int q = 0; q < 4; ++q) {
            const int lc = lc0 + q * 8;
            const float b0 = bsm[lc], b1 = bsm[lc + 1];
            float* d0 = out + (size_t)(r_top + m * 16) * OUT_W + n * DOUT + o_base + lc;
            float* d1 = d0 + 8 * OUT_W;
            float2 v0 = { c[m][q][0] + b0, c[m][q][1] + b1 };
            float2 v1 = { c[m][q][2] + b0, c[m][q][3] + b1 };
            *reinterpret_cast<float2*>(d0) = v0;
            *reinterpret_cast<float2*>(d1) = v1;
        }
    }
}

// ---------------------------------------------------------------------------
extern "C" void kernel_launch(void* const* d_in, const int* in_sizes, int n_in,
                              void* d_out, int out_size) {
    const float* x = (const float*)d_in[0];
    const float* W = (const float*)d_in[1];
    const float* b = (const float*)d_in[2];
    float* out = (float*)d_out;

    cudaFuncSetAttribute(node_gemm_kernel,
                         cudaFuncAttributeMaxDynamicSharedMemorySize, SMEM_TOTAL);

    wt_transpose_kernel<<<dim3(DIN / 32, DOUT / 32, N_NODES), dim3(32, 8)>>>(W);

    const int grid = N_NODES * (B_DIM / TILE_M) * (DOUT / TILE_N);  // 4096
    node_gemm_kernel<<<grid, THREADS, SMEM_TOTAL>>>(x, b, out);
}

// round 4
// speedup vs baseline: 1.0437x; 1.0437x over previous
#include <cuda_runtime.h>
#include <cstdint>

// ---------------------------------------------------------------------------
// NodePredictor: y[b,n,:] = x[b,n,:] @ W[n] + b[n], out = y reshaped [B, N*DOUT]
// B=2048, N=64, DIN=DOUT=512, fp32.
//
// sm_100 (no 'a') target: legacy path cp.async + ldmatrix + mma.m16n8k8 tf32.
// R4: A is RNA-rounded during staging (LDG+cvt+STS), so the consumer inner
// loop is pure ldsm+mma. B comes pre-rounded from the g_Wt prepass.
// ---------------------------------------------------------------------------

static constexpr int B_DIM   = 2048;
static constexpr int N_NODES = 64;
static constexpr int DIN     = 512;
static constexpr int DOUT    = 512;
static constexpr int OUT_W   = N_NODES * DOUT;   // 32768

static constexpr int TILE_M  = 128;
static constexpr int TILE_N  = 128;
static constexpr int TILE_K  = 32;               // 32 tf32 = 128 B row
static constexpr int K_ITERS = DIN / TILE_K;     // 16
static constexpr int THREADS = 256;
static constexpr int STAGES  = 3;

static constexpr int STAGE_BYTES = 32768;        // A 16KB + B 16KB
static constexpr int SMEM_BIAS   = STAGES * STAGE_BYTES;          // 98304
static constexpr int SMEM_TOTAL  = SMEM_BIAS + TILE_N * 4;        // +512

// 64 MB scratch: Wt[n][dout][din], tf32(RNA)-rounded fp32 bits
__device__ float g_Wt[(size_t)N_NODES * DOUT * DIN];

// ---------------------------------------------------------------------------
__device__ __forceinline__ uint32_t smem_u32(const void* p) {
    uint32_t a;
    asm("{ .reg .u64 t; cvta.to.shared.u64 t, %1; cvt.u32.u64 %0, t; }" : "=r"(a) : "l"(p));
    return a;
}
__device__ __forceinline__ uint32_t rna_tf32(float x) {
    uint32_t r;
    asm("cvt.rna.tf32.f32 %0, %1;" : "=r"(r) : "f"(x));
    return r;
}
__device__ __forceinline__ uint32_t sw128(uint32_t off) {
    return off ^ ((off >> 3) & 0x70u);
}
__device__ __forceinline__ void cp_async16(uint32_t smem_dst, const void* gmem_src) {
    asm volatile("cp.async.cg.shared.global [%0], [%1], 16;"
                 :: "r"(smem_dst), "l"(gmem_src) : "memory");
}
__device__ __forceinline__ void cp_commit() {
    asm volatile("cp.async.commit_group;" ::: "memory");
}
template <int N>
__device__ __forceinline__ void cp_wait() {
    asm volatile("cp.async.wait_group %0;" :: "n"(N) : "memory");
}
__device__ __forceinline__ void ldsm_x4(uint32_t* r, uint32_t addr) {
    asm volatile("ldmatrix.sync.aligned.m8n8.x4.shared.b16 {%0,%1,%2,%3}, [%4];"
                 : "=r"(r[0]), "=r"(r[1]), "=r"(r[2]), "=r"(r[3]) : "r"(addr));
}
__device__ __forceinline__ void mma_tf32(float* c, const uint32_t* a, uint32_t b0, uint32_t b1) {
    asm volatile(
        "mma.sync.aligned.m16n8k8.row.col.f32.tf32.tf32.f32 "
        "{%0,%1,%2,%3}, {%4,%5,%6,%7}, {%8,%9}, {%0,%1,%2,%3};"
        : "+f"(c[0]), "+f"(c[1]), "+f"(c[2]), "+f"(c[3])
        : "r"(a[0]), "r"(a[1]), "r"(a[2]), "r"(a[3]), "r"(b0), "r"(b1));
}
__device__ __forceinline__ void sts128(uint32_t addr, uint32_t r0, uint32_t r1,
                                       uint32_t r2, uint32_t r3) {
    asm volatile("st.shared.v4.b32 [%0], {%1, %2, %3, %4};"
                 :: "r"(addr), "r"(r0), "r"(r1), "r"(r2), "r"(r3) : "memory");
}

// ---------------------------------------------------------------------------
// Pre-pass: Wt[n][o][i] = rna_tf32(W[n][i][o])
// ---------------------------------------------------------------------------
__global__ void wt_transpose_kernel(const float* __restrict__ W) {
    __shared__ float tile[32][33];
    const int n  = blockIdx.z;
    const int i0 = blockIdx.x * 32;
    const int o0 = blockIdx.y * 32;
    const int tx = threadIdx.x, ty = threadIdx.y;   // 32 x 8

    const float* src = W + ((size_t)n * DIN + i0) * DOUT + o0;
#pragma unroll
    for (int r = 0; r < 32; r += 8)
        tile[ty + r][tx] = src[(size_t)(ty + r) * DOUT + tx];
    __syncthreads();

    float* dst = g_Wt + ((size_t)n * DOUT + o0) * DIN + i0;
#pragma unroll
    for (int r = 0; r < 32; r += 8)
        dst[(size_t)(ty + r) * DIN + tx] = __uint_as_float(rna_tf32(tile[tx][ty + r]));
}

// ---------------------------------------------------------------------------
// Main GEMM: CTA = [128M x 128N] tile of one node. 8 warps, warptile 64x32.
// ---------------------------------------------------------------------------
__global__ __launch_bounds__(THREADS, 2)
void node_gemm_kernel(const float* __restrict__ x, const float* __restrict__ bias,
                      float* __restrict__ out) {
    extern __shared__ char smem[];
    const uint32_t sbase = smem_u32(smem);
    const int tid  = threadIdx.x;
    const int wid  = tid >> 5;
    const int lane = tid & 31;

    // block decode: nt fastest (L2 reuse of A slab), then mt, then node
    const int bx = blockIdx.x;
    const int n  = bx >> 6;
    const int mt = (bx >> 2) & 15;
    const int nt = bx & 3;
    const int m_base = mt * TILE_M;
    const int o_base = nt * TILE_N;

    if (tid < TILE_N)
        reinterpret_cast<float*>(smem + SMEM_BIAS)[tid] = bias[n * DOUT + o_base + tid];

    // ---- staging: thread t handles row t/2, 16B-chunks (t&1)*4 .. +3
    const int st_row = tid >> 1;
    const int st_cb  = (tid & 1) * 4;
    const float* a_src = x + ((size_t)(m_base + st_row) * N_NODES + n) * DIN + st_cb * 4;
    const float* b_src = g_Wt + ((size_t)(n * DOUT + o_base + st_row)) * DIN + st_cb * 4;
    uint32_t st_dst[4];
#pragma unroll
    for (int j = 0; j < 4; ++j)
        st_dst[j] = sw128((uint32_t)st_row * 128u + (uint32_t)(st_cb + j) * 16u);

    // B via cp.async (already tf32-rounded in g_Wt)
    auto issue_b = [&](int stage, int kc) {
        const uint32_t bs = sbase + stage * STAGE_BYTES + 16384;
        const float* bp = b_src + kc * TILE_K;
#pragma unroll
        for (int j = 0; j < 4; ++j) cp_async16(bs + st_dst[j], bp + j * 4);
        cp_commit();
    };
    // A: LDG into regs (held), later cvt+STS
    auto ldg_a = [&](float4* v, int kc) {
        const float4* ap = reinterpret_cast<const float4*>(a_src + kc * TILE_K);
#pragma unroll
        for (int j = 0; j < 4; ++j) v[j] = ap[j];
    };
    auto sts_a = [&](int stage, const float4* v) {
        const uint32_t as = sbase + stage * STAGE_BYTES;
#pragma unroll
        for (int j = 0; j < 4; ++j)
            sts128(as + st_dst[j], rna_tf32(v[j].x), rna_tf32(v[j].y),
                   rna_tf32(v[j].z), rna_tf32(v[j].w));
    };

    // ---- ldmatrix lane address components (verified mapping from R2)
    const int wm = wid >> 2;       // 0..1  (M)
    const int wn = wid & 3;        // 0..3  (N)
    const uint32_t a_row  = (uint32_t)(wm * 64 + (lane & 15));
    const uint32_t a_cadd = (uint32_t)(lane >> 4);
    const uint32_t b_row  = (uint32_t)(wn * 32 + ((lane >> 4) << 3) + (lane & 7));
    const uint32_t b_cadd = (uint32_t)((lane >> 3) & 1);

    float c[4][4][4];
#pragma unroll
    for (int i = 0; i < 4; ++i)
#pragma unroll
        for (int j = 0; j < 4; ++j)
#pragma unroll
            for (int k = 0; k < 4; ++k) c[i][j][k] = 0.0f;

    // pure ldsm+mma consumer (no cvt — both operands pre-rounded in smem)
    auto compute = [&](int stage) {
        const uint32_t as = sbase + stage * STAGE_BYTES;
        const uint32_t bs = as + 16384;
#pragma unroll
        for (int ks = 0; ks < 4; ++ks) {
            const uint32_t ac = 2 * ks + a_cadd;
            const uint32_t bc = 2 * ks + b_cadd;
            uint32_t a[4][4];
#pragma unroll
            for (int m = 0; m < 4; ++m)
                ldsm_x4(a[m], as + sw128((a_row + m * 16) * 128u + ac * 16u));
            uint32_t bq[8];
            ldsm_x4(bq + 0, bs + sw128((b_row +  0) * 128u + bc * 16u));
            ldsm_x4(bq + 4, bs + sw128((b_row + 16) * 128u + bc * 16u));
#pragma unroll
            for (int m = 0; m < 4; ++m)
#pragma unroll
                for (int q = 0; q < 4; ++q)
                    mma_tf32(c[m][q], a[m], bq[2 * q], bq[2 * q + 1]);
        }
    };

    // ---- prologue: fill stages 0 and 1 (A: LDG+cvt+STS, B: cp.async)
    {
        float4 v0[4], v1[4];
        ldg_a(v0, 0);
        ldg_a(v1, 1);
        issue_b(0, 0);
        issue_b(1, 1);
        sts_a(0, v0);
        sts_a(1, v1);
        cp_wait<0>();
        __syncthreads();
    }

    int s = 0;
    for (int kc = 0; kc < K_ITERS; ++kc) {
        const int s_issue = (s + 2 >= STAGES) ? s + 2 - STAGES : s + 2;

        float4 vpre[4];
        const bool pre = (kc + 2 < K_ITERS);
        if (pre) {
            issue_b(s_issue, kc + 2);   // async B for stage kc+2
            ldg_a(vpre, kc + 2);        // LDG A, held in regs across compute
        }

        compute(s);                     // 4 ks of ldsm+mma, hides LDG latency

        if (pre) sts_a(s_issue, vpre);  // round + store A for stage kc+2

        if (kc + 1 < K_ITERS) {
            if (kc + 1 == K_ITERS - 1) cp_wait<0>(); else cp_wait<1>();
            __syncthreads();
        }
        s = (s + 1 == STAGES) ? 0 : s + 1;
    }

    // ---- epilogue: add bias, store (c0,c1)/(c2,c3) as float2
    const float* bsm = reinterpret_cast<const float*>(smem + SMEM_BIAS);
    const int r_top = m_base + wm * 64 + (lane >> 2);
    const int lc0   = wn * 32 + (lane & 3) * 2;
#pragma unroll
    for (int m = 0; m < 4; ++m) {
#pragma unroll
        for (int q = 0; q < 4; ++q) {
            const int lc = lc0 + q * 8;
            const float b0 = bsm[lc], b1 = bsm[lc + 1];
            float* d0 = out + (size_t)(r_top + m * 16) * OUT_W + n * DOUT + o_base + lc;
            float* d1 = d0 + 8 * OUT_W;
            float2 v0 = { c[m][q][0] + b0, c[m][q][1] + b1 };
            float2 v1 = { c[m][q][2] + b0, c[m][q][3] + b1 };
            *reinterpret_cast<float2*>(d0) = v0;
            *reinterpret_cast<float2*>(d1) = v1;
        }
    }
}

// ---------------------------------------------------------------------------
extern "C" void kernel_launch(void* const* d_in, const int* in_sizes, int n_in,
                              void* d_out, int out_size) {
    const float* x = (const float*)d_in[0];
    const float* W = (const float*)d_in[1];
    const float* b = (const float*)d_in[2];
    float* out = (float*)d_out;

    cudaFuncSetAttribute(node_gemm_kernel,
                         cudaFuncAttributeMaxDynamicSharedMemorySize, SMEM_TOTAL);

    wt_transpose_kernel<<<dim3(DIN / 32, DOUT / 32, N_NODES), dim3(32, 8)>>>(W);

    const int grid = N_NODES * (B_DIM / TILE_M) * (DOUT / TILE_N);  // 4096
    node_gemm_kernel<<<grid, THREADS, SMEM_TOTAL>>>(x, b, out);
}

// round 5
// speedup vs baseline: 1.0443x; 1.0006x over previous
#include <cuda_runtime.h>
#include <cstdint>

// ---------------------------------------------------------------------------
// NodePredictor: y[b,n,:] = x[b,n,:] @ W[n] + b[n], out = y reshaped [B, N*DOUT]
// B=2048, N=64, DIN=DOUT=512, fp32.
//
// sm_100 (no 'a') target: legacy path cp.async + ldmatrix + mma.m16n8k8 tf32.
// R4: A is RNA-rounded during staging (LDG+cvt+STS), so the consumer inner
// loop is pure ldsm+mma. B comes pre-rounded from the g_Wt prepass.
// ---------------------------------------------------------------------------

static constexpr int B_DIM   = 2048;
static constexpr int N_NODES = 64;
static constexpr int DIN     = 512;
static constexpr int DOUT    = 512;
static constexpr int OUT_W   = N_NODES * DOUT;   // 32768

static constexpr int TILE_M  = 128;
static constexpr int TILE_N  = 128;
static constexpr int TILE_K  = 32;               // 32 tf32 = 128 B row
static constexpr int K_ITERS = DIN / TILE_K;     // 16
static constexpr int THREADS = 256;
static constexpr int STAGES  = 3;

static constexpr int STAGE_BYTES = 32768;        // A 16KB + B 16KB
static constexpr int SMEM_BIAS   = STAGES * STAGE_BYTES;          // 98304
static constexpr int SMEM_TOTAL  = SMEM_BIAS + TILE_N * 4;        // +512

// 64 MB scratch: Wt[n][dout][din], tf32(RNA)-rounded fp32 bits
__device__ float g_Wt[(size_t)N_NODES * DOUT * DIN];

// ---------------------------------------------------------------------------
__device__ __forceinline__ uint32_t smem_u32(const void* p) {
    uint32_t a;
    asm("{ .reg .u64 t; cvta.to.shared.u64 t, %1; cvt.u32.u64 %0, t; }" : "=r"(a) : "l"(p));
    return a;
}
__device__ __forceinline__ uint32_t rna_tf32(float x) {
    uint32_t r;
    asm("cvt.rna.tf32.f32 %0, %1;" : "=r"(r) : "f"(x));
    return r;
}
__device__ __forceinline__ uint32_t sw128(uint32_t off) {
    return off ^ ((off >> 3) & 0x70u);
}
__device__ __forceinline__ void cp_async16(uint32_t smem_dst, const void* gmem_src) {
    asm volatile("cp.async.cg.shared.global [%0], [%1], 16;"
                 :: "r"(smem_dst), "l"(gmem_src) : "memory");
}
__device__ __forceinline__ void cp_commit() {
    asm volatile("cp.async.commit_group;" ::: "memory");
}
template <int N>
__device__ __forceinline__ void cp_wait() {
    asm volatile("cp.async.wait_group %0;" :: "n"(N) : "memory");
}
__device__ __forceinline__ void ldsm_x4(uint32_t* r, uint32_t addr) {
    asm volatile("ldmatrix.sync.aligned.m8n8.x4.shared.b16 {%0,%1,%2,%3}, [%4];"
                 : "=r"(r[0]), "=r"(r[1]), "=r"(r[2]), "=r"(r[3]) : "r"(addr));
}
__device__ __forceinline__ void mma_tf32(float* c, const uint32_t* a, uint32_t b0, uint32_t b1) {
    asm volatile(
        "mma.sync.aligned.m16n8k8.row.col.f32.tf32.tf32.f32 "
        "{%0,%1,%2,%3}, {%4,%5,%6,%7}, {%8,%9}, {%0,%1,%2,%3};"
        : "+f"(c[0]), "+f"(c[1]), "+f"(c[2]), "+f"(c[3])
        : "r"(a[0]), "r"(a[1]), "r"(a[2]), "r"(a[3]), "r"(b0), "r"(b1));
}
__device__ __forceinline__ void sts128(uint32_t addr, uint32_t r0, uint32_t r1,
                                       uint32_t r2, uint32_t r3) {
    asm volatile("st.shared.v4.b32 [%0], {%1, %2, %3, %4};"
                 :: "r"(addr), "r"(r0), "r"(r1), "r"(r2), "r"(r3) : "memory");
}

// ---------------------------------------------------------------------------
// Pre-pass: Wt[n][o][i] = rna_tf32(W[n][i][o])
// ---------------------------------------------------------------------------
__global__ void wt_transpose_kernel(const float* __restrict__ W) {
    __shared__ float tile[32][33];
    const int n  = blockIdx.z;
    const int i0 = blockIdx.x * 32;
    const int o0 = blockIdx.y * 32;
    const int tx = threadIdx.x, ty = threadIdx.y;   // 32 x 8

    const float* src = W + ((size_t)n * DIN + i0) * DOUT + o0;
#pragma unroll
    for (int r = 0; r < 32; r += 8)
        tile[ty + r][tx] = src[(size_t)(ty + r) * DOUT + tx];
    __syncthreads();

    float* dst = g_Wt + ((size_t)n * DOUT + o0) * DIN + i0;
#pragma unroll
    for (int r = 0; r < 32; r += 8)
        dst[(size_t)(ty + r) * DIN + tx] = __uint_as_float(rna_tf32(tile[tx][ty + r]));
}

// ---------------------------------------------------------------------------
// Main GEMM: CTA = [128M x 128N] tile of one node. 8 warps, warptile 64x32.
// ---------------------------------------------------------------------------
__global__ __launch_bounds__(THREADS, 2)
void node_gemm_kernel(const float* __restrict__ x, const float* __restrict__ bias,
                      float* __restrict__ out) {
    extern __shared__ char smem[];
    const uint32_t sbase = smem_u32(smem);
    const int tid  = threadIdx.x;
    const int wid  = tid >> 5;
    const int lane = tid & 31;

    // block decode: nt fastest (L2 reuse of A slab), then mt, then node
    const int bx = blockIdx.x;
    const int n  = bx >> 6;
    const int mt = (bx >> 2) & 15;
    const int nt = bx & 3;
    const int m_base = mt * TILE_M;
    const int o_base = nt * TILE_N;

    if (tid < TILE_N)
        reinterpret_cast<float*>(smem + SMEM_BIAS)[tid] = bias[n * DOUT + o_base + tid];

    // ---- staging: thread t handles row t/2, 16B-chunks (t&1)*4 .. +3
    const int st_row = tid >> 1;
    const int st_cb  = (tid & 1) * 4;
    const float* a_src = x + ((size_t)(m_base + st_row) * N_NODES + n) * DIN + st_cb * 4;
    const float* b_src = g_Wt + ((size_t)(n * DOUT + o_base + st_row)) * DIN + st_cb * 4;
    uint32_t st_dst[4];
#pragma unroll
    for (int j = 0; j < 4; ++j)
        st_dst[j] = sw128((uint32_t)st_row * 128u + (uint32_t)(st_cb + j) * 16u);

    // B via cp.async (already tf32-rounded in g_Wt)
    auto issue_b = [&](int stage, int kc) {
        const uint32_t bs = sbase + stage * STAGE_BYTES + 16384;
        const float* bp = b_src + kc * TILE_K;
#pragma unroll
        for (int j = 0; j < 4; ++j) cp_async16(bs + st_dst[j], bp + j * 4);
        cp_commit();
    };
    // A: LDG into regs (held), later cvt+STS
    auto ldg_a = [&](float4* v, int kc) {
        const float4* ap = reinterpret_cast<const float4*>(a_src + kc * TILE_K);
#pragma unroll
        for (int j = 0; j < 4; ++j) v[j] = ap[j];
    };
    auto sts_a = [&](int stage, const float4* v) {
        const uint32_t as = sbase + stage * STAGE_BYTES;
#pragma unroll
        for (int j = 0; j < 4; ++j)
            sts128(as + st_dst[j], rna_tf32(v[j].x), rna_tf32(v[j].y),
                   rna_tf32(v[j].z), rna_tf32(v[j].w));
    };

    // ---- ldmatrix lane address components (verified mapping from R2)
    const int wm = wid >> 2;       // 0..1  (M)
    const int wn = wid & 3;        // 0..3  (N)
    const uint32_t a_row  = (uint32_t)(wm * 64 + (lane & 15));
    const uint32_t a_cadd = (uint32_t)(lane >> 4);
    const uint32_t b_row  = (uint32_t)(wn * 32 + ((lane >> 4) << 3) + (lane & 7));
    const uint32_t b_cadd = (uint32_t)((lane >> 3) & 1);

    float c[4][4][4];
#pragma unroll
    for (int i = 0; i < 4; ++i)
#pragma unroll
        for (int j = 0; j < 4; ++j)
#pragma unroll
            for (int k = 0; k < 4; ++k) c[i][j][k] = 0.0f;

    // pure ldsm+mma consumer (no cvt — both operands pre-rounded in smem)
    auto compute = [&](int stage) {
        const uint32_t as = sbase + stage * STAGE_BYTES;
        const uint32_t bs = as + 16384;
#pragma unroll
        for (int ks = 0; ks < 4; ++ks) {
            const uint32_t ac = 2 * ks + a_cadd;
            const uint32_t bc = 2 * ks + b_cadd;
            uint32_t a[4][4];
#pragma unroll
            for (int m = 0; m < 4; ++m)
                ldsm_x4(a[m], as + sw128((a_row + m * 16) * 128u + ac * 16u));
            uint32_t bq[8];
            ldsm_x4(bq + 0, bs + sw128((b_row +  0) * 128u + bc * 16u));
            ldsm_x4(bq + 4, bs + sw128((b_row + 16) * 128u + bc * 16u));
#pragma unroll
            for (int m = 0; m < 4; ++m)
#pragma unroll
                for (int q = 0; q < 4; ++q)
                    mma_tf32(c[m][q], a[m], bq[2 * q], bq[2 * q + 1]);
        }
    };

    // ---- prologue: fill stages 0 and 1 (A: LDG+cvt+STS, B: cp.async)
    {
        float4 v0[4], v1[4];
        ldg_a(v0, 0);
        ldg_a(v1, 1);
        issue_b(0, 0);
        issue_b(1, 1);
        sts_a(0, v0);
        sts_a(1, v1);
        cp_wait<0>();
        __syncthreads();
    }

    int s = 0;
    for (int kc = 0; kc < K_ITERS; ++kc) {
        const int s_issue = (s + 2 >= STAGES) ? s + 2 - STAGES : s + 2;

        float4 vpre[4];
        const bool pre = (kc + 2 < K_ITERS);
        if (pre) {
            issue_b(s_issue, kc + 2);   // async B for stage kc+2
            ldg_a(vpre, kc + 2);        // LDG A, held in regs across compute
        }

        compute(s);                     // 4 ks of ldsm+mma, hides LDG latency

        if (pre) sts_a(s_issue, vpre);  // round + store A for stage kc+2

        if (kc + 1 < K_ITERS) {
            if (kc + 1 == K_ITERS - 1) cp_wait<0>(); else cp_wait<1>();
            __syncthreads();
        }
        s = (s + 1 == STAGES) ? 0 : s + 1;
    }

    // ---- epilogue: add bias, store (c0,c1)/(c2,c3) as float2
    const float* bsm = reinterpret_cast<const float*>(smem + SMEM_BIAS);
    const int r_top = m_base + wm * 64 + (lane >> 2);
    const int lc0   = wn * 32 + (lane & 3) * 2;
#pragma unroll
    for (int m = 0; m < 4; ++m) {
#pragma unroll
        for (int q = 0; q < 4; ++q) {
            const int lc = lc0 + q * 8;
            const float b0 = bsm[lc], b1 = bsm[lc + 1];
            float* d0 = out + (size_t)(r_top + m * 16) * OUT_W + n * DOUT + o_base + lc;
            float* d1 = d0 + 8 * OUT_W;
            float2 v0 = { c[m][q][0] + b0, c[m][q][1] + b1 };
            float2 v1 = { c[m][q][2] + b0, c[m][q][3] + b1 };
            *reinterpret_cast<float2*>(d0) = v0;
            *reinterpret_cast<float2*>(d1) = v1;
        }
    }
}

// ---------------------------------------------------------------------------
extern "C" void kernel_launch(void* const* d_in, const int* in_sizes, int n_in,
                              void* d_out, int out_size) {
    const float* x = (const float*)d_in[0];
    const float* W = (const float*)d_in[1];
    const float* b = (const float*)d_in[2];
    float* out = (float*)d_out;

    cudaFuncSetAttribute(node_gemm_kernel,
                         cudaFuncAttributeMaxDynamicSharedMemorySize, SMEM_TOTAL);

    wt_transpose_kernel<<<dim3(DIN / 32, DOUT / 32, N_NODES), dim3(32, 8)>>>(W);

    const int grid = N_NODES * (B_DIM / TILE_M) * (DOUT / TILE_N);  // 4096
    node_gemm_kernel<<<grid, THREADS, SMEM_TOTAL>>>(x, b, out);
}

// round 6
// speedup vs baseline: 1.0458x; 1.0014x over previous
#include <cuda_runtime.h>
#include <cstdint>

// ---------------------------------------------------------------------------
// NodePredictor: y[b,n,:] = x[b,n,:] @ W[n] + b[n], out = y reshaped [B, N*DOUT]
// B=2048, N=64, DIN=DOUT=512, fp32.
//
// sm_100 (no 'a') target: legacy path cp.async + ldmatrix + mma.m16n8k8 tf32.
// R4: A is RNA-rounded during staging (LDG+cvt+STS), so the consumer inner
// loop is pure ldsm+mma. B comes pre-rounded from the g_Wt prepass.
// ---------------------------------------------------------------------------

static constexpr int B_DIM   = 2048;
static constexpr int N_NODES = 64;
static constexpr int DIN     = 512;
static constexpr int DOUT    = 512;
static constexpr int OUT_W   = N_NODES * DOUT;   // 32768

static constexpr int TILE_M  = 128;
static constexpr int TILE_N  = 128;
static constexpr int TILE_K  = 32;               // 32 tf32 = 128 B row
static constexpr int K_ITERS = DIN / TILE_K;     // 16
static constexpr int THREADS = 256;
static constexpr int STAGES  = 3;

static constexpr int STAGE_BYTES = 32768;        // A 16KB + B 16KB
static constexpr int SMEM_BIAS   = STAGES * STAGE_BYTES;          // 98304
static constexpr int SMEM_TOTAL  = SMEM_BIAS + TILE_N * 4;        // +512

// 64 MB scratch: Wt[n][dout][din], tf32(RNA)-rounded fp32 bits
__device__ float g_Wt[(size_t)N_NODES * DOUT * DIN];

// ---------------------------------------------------------------------------
__device__ __forceinline__ uint32_t smem_u32(const void* p) {
    uint32_t a;
    asm("{ .reg .u64 t; cvta.to.shared.u64 t, %1; cvt.u32.u64 %0, t; }" : "=r"(a) : "l"(p));
    return a;
}
__device__ __forceinline__ uint32_t rna_tf32(float x) {
    uint32_t r;
    asm("cvt.rna.tf32.f32 %0, %1;" : "=r"(r) : "f"(x));
    return r;
}
__device__ __forceinline__ uint32_t sw128(uint32_t off) {
    return off ^ ((off >> 3) & 0x70u);
}
__device__ __forceinline__ void cp_async16(uint32_t smem_dst, const void* gmem_src) {
    asm volatile("cp.async.cg.shared.global [%0], [%1], 16;"
                 :: "r"(smem_dst), "l"(gmem_src) : "memory");
}
__device__ __forceinline__ void cp_commit() {
    asm volatile("cp.async.commit_group;" ::: "memory");
}
template <int N>
__device__ __forceinline__ void cp_wait() {
    asm volatile("cp.async.wait_group %0;" :: "n"(N) : "memory");
}
__device__ __forceinline__ void ldsm_x4(uint32_t* r, uint32_t addr) {
    asm volatile("ldmatrix.sync.aligned.m8n8.x4.shared.b16 {%0,%1,%2,%3}, [%4];"
                 : "=r"(r[0]), "=r"(r[1]), "=r"(r[2]), "=r"(r[3]) : "r"(addr));
}
__device__ __forceinline__ void mma_tf32(float* c, const uint32_t* a, uint32_t b0, uint32_t b1) {
    asm volatile(
        "mma.sync.aligned.m16n8k8.row.col.f32.tf32.tf32.f32 "
        "{%0,%1,%2,%3}, {%4,%5,%6,%7}, {%8,%9}, {%0,%1,%2,%3};"
        : "+f"(c[0]), "+f"(c[1]), "+f"(c[2]), "+f"(c[3])
        : "r"(a[0]), "r"(a[1]), "r"(a[2]), "r"(a[3]), "r"(b0), "r"(b1));
}
__device__ __forceinline__ void sts128(uint32_t addr, uint32_t r0, uint32_t r1,
                                       uint32_t r2, uint32_t r3) {
    asm volatile("st.shared.v4.b32 [%0], {%1, %2, %3, %4};"
                 :: "r"(addr), "r"(r0), "r"(r1), "r"(r2), "r"(r3) : "memory");
}

// ---------------------------------------------------------------------------
// Pre-pass: Wt[n][o][i] = rna_tf32(W[n][i][o])
// ---------------------------------------------------------------------------
__global__ void wt_transpose_kernel(const float* __restrict__ W) {
    __shared__ float tile[32][33];
    const int n  = blockIdx.z;
    const int i0 = blockIdx.x * 32;
    const int o0 = blockIdx.y * 32;
    const int tx = threadIdx.x, ty = threadIdx.y;   // 32 x 8

    const float* src = W + ((size_t)n * DIN + i0) * DOUT + o0;
#pragma unroll
    for (int r = 0; r < 32; r += 8)
        tile[ty + r][tx] = src[(size_t)(ty + r) * DOUT + tx];
    __syncthreads();

    float* dst = g_Wt + ((size_t)n * DOUT + o0) * DIN + i0;
#pragma unroll
    for (int r = 0; r < 32; r += 8)
        dst[(size_t)(ty + r) * DIN + tx] = __uint_as_float(rna_tf32(tile[tx][ty + r]));
}

// ---------------------------------------------------------------------------
// Main GEMM: CTA = [128M x 128N] tile of one node. 8 warps, warptile 64x32.
// ---------------------------------------------------------------------------
__global__ __launch_bounds__(THREADS, 2)
void node_gemm_kernel(const float* __restrict__ x, const float* __restrict__ bias,
                      float* __restrict__ out) {
    extern __shared__ char smem[];
    const uint32_t sbase = smem_u32(smem);
    const int tid  = threadIdx.x;
    const int wid  = tid >> 5;
    const int lane = tid & 31;

    // block decode: nt fastest (L2 reuse of A slab), then mt, then node
    const int bx = blockIdx.x;
    const int n  = bx >> 6;
    const int mt = (bx >> 2) & 15;
    const int nt = bx & 3;
    const int m_base = mt * TILE_M;
    const int o_base = nt * TILE_N;

    if (tid < TILE_N)
        reinterpret_cast<float*>(smem + SMEM_BIAS)[tid] = bias[n * DOUT + o_base + tid];

    // ---- staging: thread t handles row t/2, 16B-chunks (t&1)*4 .. +3
    const int st_row = tid >> 1;
    const int st_cb  = (tid & 1) * 4;
    const float* a_src = x + ((size_t)(m_base + st_row) * N_NODES + n) * DIN + st_cb * 4;
    const float* b_src = g_Wt + ((size_t)(n * DOUT + o_base + st_row)) * DIN + st_cb * 4;
    uint32_t st_dst[4];
#pragma unroll
    for (int j = 0; j < 4; ++j)
        st_dst[j] = sw128((uint32_t)st_row * 128u + (uint32_t)(st_cb + j) * 16u);

    // B via cp.async (already tf32-rounded in g_Wt)
    auto issue_b = [&](int stage, int kc) {
        const uint32_t bs = sbase + stage * STAGE_BYTES + 16384;
        const float* bp = b_src + kc * TILE_K;
#pragma unroll
        for (int j = 0; j < 4; ++j) cp_async16(bs + st_dst[j], bp + j * 4);
        cp_commit();
    };
    // A: LDG into regs (held), later cvt+STS
    auto ldg_a = [&](float4* v, int kc) {
        const float4* ap = reinterpret_cast<const float4*>(a_src + kc * TILE_K);
#pragma unroll
        for (int j = 0; j < 4; ++j) v[j] = ap[j];
    };
    auto sts_a = [&](int stage, const float4* v) {
        const uint32_t as = sbase + stage * STAGE_BYTES;
#pragma unroll
        for (int j = 0; j < 4; ++j)
            sts128(as + st_dst[j], rna_tf32(v[j].x), rna_tf32(v[j].y),
                   rna_tf32(v[j].z), rna_tf32(v[j].w));
    };

    // ---- ldmatrix lane address components (verified mapping from R2)
    const int wm = wid >> 2;       // 0..1  (M)
    const int wn = wid & 3;        // 0..3  (N)
    const uint32_t a_row  = (uint32_t)(wm * 64 + (lane & 15));
    const uint32_t a_cadd = (uint32_t)(lane >> 4);
    const uint32_t b_row  = (uint32_t)(wn * 32 + ((lane >> 4) << 3) + (lane & 7));
    const uint32_t b_cadd = (uint32_t)((lane >> 3) & 1);

    float c[4][4][4];
#pragma unroll
    for (int i = 0; i < 4; ++i)
#pragma unroll
        for (int j = 0; j < 4; ++j)
#pragma unroll
            for (int k = 0; k < 4; ++k) c[i][j][k] = 0.0f;

    // pure ldsm+mma consumer (no cvt — both operands pre-rounded in smem)
    auto compute = [&](int stage) {
        const uint32_t as = sbase + stage * STAGE_BYTES;
        const uint32_t bs = as + 16384;
#pragma unroll
        for (int ks = 0; ks < 4; ++ks) {
            const uint32_t ac = 2 * ks + a_cadd;
            const uint32_t bc = 2 * ks + b_cadd;
            uint32_t a[4][4];
#pragma unroll
            for (int m = 0; m < 4; ++m)
                ldsm_x4(a[m], as + sw128((a_row + m * 16) * 128u + ac * 16u));
            uint32_t bq[8];
            ldsm_x4(bq + 0, bs + sw128((b_row +  0) * 128u + bc * 16u));
            ldsm_x4(bq + 4, bs + sw128((b_row + 16) * 128u + bc * 16u));
#pragma unroll
            for (int m = 0; m < 4; ++m)
#pragma unroll
                for (int q = 0; q < 4; ++q)
                    mma_tf32(c[m][q], a[m], bq[2 * q], bq[2 * q + 1]);
        }
    };

    // ---- prologue: fill stages 0 and 1 (A: LDG+cvt+STS, B: cp.async)
    {
        float4 v0[4], v1[4];
        ldg_a(v0, 0);
        ldg_a(v1, 1);
        issue_b(0, 0);
        issue_b(1, 1);
        sts_a(0, v0);
        sts_a(1, v1);
        cp_wait<0>();
        __syncthreads();
    }

    int s = 0;
    for (int kc = 0; kc < K_ITERS; ++kc) {
        const int s_issue = (s + 2 >= STAGES) ? s + 2 - STAGES : s + 2;

        float4 vpre[4];
        const bool pre = (kc + 2 < K_ITERS);
        if (pre) {
            issue_b(s_issue, kc + 2);   // async B for stage kc+2
            ldg_a(vpre, kc + 2);        // LDG A, held in regs across compute
        }

        compute(s);                     // 4 ks of ldsm+mma, hides LDG latency

        if (pre) sts_a(s_issue, vpre);  // round + store A for stage kc+2

        if (kc + 1 < K_ITERS) {
            if (kc + 1 == K_ITERS - 1) cp_wait<0>(); else cp_wait<1>();
            __syncthreads();
        }
        s = (s + 1 == STAGES) ? 0 : s + 1;
    }

    // ---- epilogue: add bias, store (c0,c1)/(c2,c3) as float2
    const float* bsm = reinterpret_cast<const float*>(smem + SMEM_BIAS);
    const int r_top = m_base + wm * 64 + (lane >> 2);
    const int lc0   = wn * 32 + (lane & 3) * 2;
#pragma unroll
    for (int m = 0; m < 4; ++m) {
#pragma unroll
        for (int q = 0; q < 4; ++q) {
            const int lc = lc0 + q * 8;
            const float b0 = bsm[lc], b1 = bsm[lc + 1];
            float* d0 = out + (size_t)(r_top + m * 16) * OUT_W + n * DOUT + o_base + lc;
            float* d1 = d0 + 8 * OUT_W;
            float2 v0 = { c[m][q][0] + b0, c[m][q][1] + b1 };
            float2 v1 = { c[m][q][2] + b0, c[m][q][3] + b1 };
            *reinterpret_cast<float2*>(d0) = v0;
            *reinterpret_cast<float2*>(d1) = v1;
        }
    }
}

// ---------------------------------------------------------------------------
extern "C" void kernel_launch(void* const* d_in, const int* in_sizes, int n_in,
                              void* d_out, int out_size) {
    const float* x = (const float*)d_in[0];
    const float* W = (const float*)d_in[1];
    const float* b = (const float*)d_in[2];
    float* out = (float*)d_out;

    cudaFuncSetAttribute(node_gemm_kernel,
                         cudaFuncAttributeMaxDynamicSharedMemorySize, SMEM_TOTAL);

    wt_transpose_kernel<<<dim3(DIN / 32, DOUT / 32, N_NODES), dim3(32, 8)>>>(W);

    const int grid = N_NODES * (B_DIM / TILE_M) * (DOUT / TILE_N);  // 4096
    node_gemm_kernel<<<grid, THREADS, SMEM_TOTAL>>>(x, b, out);
}